// round 10
// baseline (speedup 1.0000x reference)
#include <cuda_runtime.h>
#include <math.h>

#define BSZ    128
#define MAXLEN 256
#define DCHAR  256
#define DHID   1024
#define VOC    512
#define BT     (BSZ * MAXLEN)   // 32768
#define BH     (BSZ * DHID)     // 131072

// ---------------------------------------------------------------------------
// Scratch (allocation-free: __device__ globals)
// ---------------------------------------------------------------------------
__device__ float g_xp_enc[BT * DHID];
__device__ float g_xp_dec[BT * DHID];
__device__ float g_states[BT * DHID];
__device__ float g_hT0[DHID * BSZ];     // transposed hidden ping [k][b]
__device__ float g_hT1[DHID * BSZ];     // transposed hidden pong [k][b]

// Per-CTA publish flags: [mi][ni], 128B (32 u32) apart. Monotone across
// graph replays (each CTA advances its own flag by exactly 513 per run).
__device__ unsigned g_flag[4 * 32 * 32];

// ---------------------------------------------------------------------------
// f32x2 helpers
// ---------------------------------------------------------------------------
__device__ __forceinline__ unsigned long long dupf(float x)
{
    unsigned long long r;
    asm("mov.b64 %0,{%1,%1};" : "=l"(r) : "f"(x));
    return r;
}
__device__ __forceinline__ void ffma2(unsigned long long& a,
                                      unsigned long long x, unsigned long long y)
{
    asm("fma.rn.f32x2 %0,%1,%2,%0;" : "+l"(a) : "l"(x), "l"(y));
}
__device__ __forceinline__ void add2(unsigned long long& a, unsigned long long x)
{
    asm("add.rn.f32x2 %0,%0,%1;" : "+l"(a) : "l"(x));
}
__device__ __forceinline__ float2 u64_to_f2(unsigned long long v)
{
    float2 f;
    asm("mov.b64 {%0,%1},%2;" : "=f"(f.x), "=f"(f.y) : "l"(v));
    return f;
}
__device__ __forceinline__ unsigned ld_acq(const unsigned* p)
{
    unsigned v;
    asm volatile("ld.acquire.gpu.global.u32 %0,[%1];" : "=r"(v) : "l"(p) : "memory");
    return v;
}

// ---------------------------------------------------------------------------
// Tiled SGEMM with row gather (v5, unchanged — near FFMA2 floor):
//   C[row, n] = sum_k A[src(row), k] * B[n, k] + bias1[n] (+ bias2[n])
// ---------------------------------------------------------------------------
#define GBM 64
#define GBN 64
#define GBK 16

__global__ void gemm_gather_kernel(const float* __restrict__ A, int lda,
                                   const int* __restrict__ tokens, int gmode, int T,
                                   const float* __restrict__ B,
                                   const float* __restrict__ bias1,
                                   const float* __restrict__ bias2,
                                   float* __restrict__ C,
                                   int N, int K)
{
    __shared__ __align__(16) float As[GBK][GBM + 4];
    __shared__ __align__(16) float Bs[GBK][GBN + 4];
    __shared__ int rowsrc[GBM];

    const int bm  = blockIdx.y * GBM;
    const int bn  = blockIdx.x * GBN;
    const int tid = threadIdx.x;

    if (tid < GBM) {
        int row = bm + tid;
        int src = row;
        if (gmode == 1) {
            src = tokens[row];
        } else if (gmode == 2) {
            int t = row % T;
            src = (t == 0) ? -1 : tokens[row - 1];
        }
        rowsrc[tid] = src;
    }
    __syncthreads();

    const int tm = (tid >> 4) * 4;
    const int tn = (tid & 15) * 4;

    unsigned long long acc2[2][4] = {};   // [m-pair][n]

    for (int k0 = 0; k0 < K; k0 += GBK) {
        #pragma unroll
        for (int i = 0; i < 4; i++) {
            int idx = tid + i * 256;
            int m = idx >> 4, kk = idx & 15;
            int src = rowsrc[m];
            As[kk][m] = (src < 0) ? 0.0f : A[src * lda + k0 + kk];
        }
        #pragma unroll
        for (int i = 0; i < 4; i++) {
            int idx = tid + i * 256;
            int n = idx >> 4, kk = idx & 15;
            Bs[kk][n] = B[(bn + n) * K + k0 + kk];
        }
        __syncthreads();

        #pragma unroll
        for (int kk = 0; kk < GBK; kk++) {
            unsigned long long a01 =
                *reinterpret_cast<const unsigned long long*>(&As[kk][tm]);
            unsigned long long a23 =
                *reinterpret_cast<const unsigned long long*>(&As[kk][tm + 2]);
            float4 b4 = *reinterpret_cast<const float4*>(&Bs[kk][tn]);
            unsigned long long b0 = dupf(b4.x), b1 = dupf(b4.y);
            unsigned long long b2 = dupf(b4.z), b3 = dupf(b4.w);
            ffma2(acc2[0][0], a01, b0);
            ffma2(acc2[0][1], a01, b1);
            ffma2(acc2[0][2], a01, b2);
            ffma2(acc2[0][3], a01, b3);
            ffma2(acc2[1][0], a23, b0);
            ffma2(acc2[1][1], a23, b1);
            ffma2(acc2[1][2], a23, b2);
            ffma2(acc2[1][3], a23, b3);
        }
        __syncthreads();
    }

    #pragma unroll
    for (int j = 0; j < 4; j++) {
        int n = bn + tn + j;
        float bb = (bias1 ? bias1[n] : 0.0f) + (bias2 ? bias2[n] : 0.0f);
        float2 p0 = u64_to_f2(acc2[0][j]);
        float2 p1 = u64_to_f2(acc2[1][j]);
        C[(bm + tm + 0) * N + n] = p0.x + bb;
        C[(bm + tm + 1) * N + n] = p0.y + bb;
        C[(bm + tm + 2) * N + n] = p1.x + bb;
        C[(bm + tm + 3) * N + n] = p1.y + bb;
    }
}

// ---------------------------------------------------------------------------
// Persistent recurrence kernel, v7: 512 threads (4 warps/SMSP) + 8-way
// interleaved split-k (k = 8*i + ksg). Same 14-instr/16-MAC inner loop; each
// thread does half the k of v6 -> FFMA2 floor unchanged (8192 cyc/SMSP/step),
// but 4 warps/SMSP hide the LDS latency that held v6 at issue=30%.
// Two-phase smem reduction using the two dead chunk buffers.
// ---------------------------------------------------------------------------
#define NTHREADS  512
#define WS_STRIDE 36
#define WS_F      (DHID * WS_STRIDE)    // 36864 floats (144 KB)
#define KC        128                   // staged k-chunk
#define CHUNK_F   (KC * 32)             // 4096 floats (16 KB)
#define SMEM_BYTES ((WS_F + 2 * CHUNK_F) * 4)   // 180224 B

__device__ __forceinline__ void load_whh_slice(float* Ws, const float* __restrict__ W,
                                               int ntile, int tid)
{
    for (int idx = tid; idx < 32 * 256; idx += NTHREADS) {
        int row = idx >> 8;          // 0..31 (n local)
        int c4  = idx & 255;         // 0..255 (k/4)
        float4 v = *reinterpret_cast<const float4*>(&W[(ntile + row) * DHID + c4 * 4]);
        int k = c4 * 4;
        Ws[(k + 0) * WS_STRIDE + row] = v.x;
        Ws[(k + 1) * WS_STRIDE + row] = v.y;
        Ws[(k + 2) * WS_STRIDE + row] = v.z;
        Ws[(k + 3) * WS_STRIDE + row] = v.w;
    }
}

__global__ void __launch_bounds__(NTHREADS, 1)
rnn_persistent_kernel(const float* __restrict__ xp_enc,
                      const float* __restrict__ xp_dec,
                      const float* __restrict__ enc_Whh,
                      const float* __restrict__ dec_Whh,
                      float* __restrict__ states,
                      float* __restrict__ hT0,
                      float* __restrict__ hT1)
{
    extern __shared__ float sm[];
    float* Ws = sm;                       // [1024][36]
    float* hs = sm + WS_F;                // 2 x [128 k][32 b]
    // Reduction scratch aliases the chunk buffers at times they are dead:
    //   pbufA = buffer 0 (dead during chunk-7 compute, which reads buffer 1)
    //   pbufB = buffer 1 (dead after the post-A __syncthreads)
    unsigned long long* pbufA = reinterpret_cast<unsigned long long*>(hs);
    unsigned long long* pbufB = reinterpret_cast<unsigned long long*>(hs + CHUNK_F);

    const int tid = threadIdx.x;
    const int ni = blockIdx.x, mi = blockIdx.y;
    const int btile = mi * 32, ntile = ni * 32;

    unsigned* const fl_grp  = &g_flag[mi * 32 * 32];
    unsigned* const fl_self = fl_grp + ni * 32;

    const int ksg = tid >> 6;             // 0..7 : k-interleave group
    const int gt  = tid & 63;
    const int b_local = (gt & 7) * 4;     // 4 batch rows
    const int n_local = (gt >> 3) * 4;    // 4 hidden cols

    // Epilogue mapping: tid -> (e_gt, e_j); output = 1 (b, n-pair) slot.
    const int e_gt = tid >> 3;                        // 0..63
    const int e_j  = tid & 7;                         // plane = b*2 + npair
    const int e_bl = (e_gt & 7) * 4 + (e_j >> 1);     // b local (0..31)
    const int e_nl = (e_gt >> 3) * 4 + (e_j & 1) * 2; // n local (0..30, pair base)

    // Staging: 1024 float4 slots, 2 per thread.
    const int s_k0  = tid >> 3;           // k row of slot i=0 (0..63); +64 for i=1
    const int s_col = (tid & 7) * 4;      // b column

    __shared__ unsigned s_base;
    if (tid == 0) s_base = *(volatile unsigned*)fl_self;

    // Zero this CTA's h0 slice: k in [ntile,+32), b in [btile,+32) = 256 float4.
    if (tid < 256) {
        int k = ntile + (tid >> 3);
        int col = (tid & 7) * 4;
        *reinterpret_cast<float4*>(&hT0[k * BSZ + btile + col]) =
            make_float4(0.f, 0.f, 0.f, 0.f);
    }
    __syncthreads();
    const unsigned base = s_base;

    // Publish h^0 (zeros): flag = base + 1.
    if (tid == 0) {
        __threadfence();
        *(volatile unsigned*)fl_self = base + 1;
    }

    load_whh_slice(Ws, enc_Whh, ntile, tid);
    __syncthreads();

    for (int s = 0; s < 512; s++) {
        if (s == 256) {
            load_whh_slice(Ws, dec_Whh, ntile, tid);
            __syncthreads();
        }
        const float* __restrict__ hin  = (s & 1) ? hT1 : hT0;
        float* __restrict__       hout = (s & 1) ? hT0 : hT1;
        const int t = s & 255;
        const float* __restrict__ xp = (s < 256) ? xp_enc : xp_dec;
        const unsigned tgt = base + 1 + (unsigned)s;

        // Epilogue xp prefetch (1 LDG.64/thread; independent of flags).
        float2 xr = *reinterpret_cast<const float2*>(
            &xp[((size_t)(btile + e_bl) * MAXLEN + t) * DHID + ntile + e_nl]);

        // Warp-parallel wait: lane j of warp 0 polls producer flag j.
        if (tid < 32) {
            const unsigned* p = fl_grp + tid * 32;
            unsigned v = ld_acq(p);
            while (!__all_sync(0xffffffffu, (int)(v - tgt) >= 0))
                v = ld_acq(p);
        }
        __syncthreads();

        // Stage chunk 0.
        float4 r[2];
        #pragma unroll
        for (int i = 0; i < 2; i++)
            r[i] = *reinterpret_cast<const float4*>(
                &hin[(s_k0 + i * 64) * BSZ + btile + s_col]);
        #pragma unroll
        for (int i = 0; i < 2; i++)
            *reinterpret_cast<float4*>(&hs[(s_k0 + i * 64) * 32 + s_col]) = r[i];
        __syncthreads();

        unsigned long long acc[4][2] = {};   // [b][n-pair]

        #pragma unroll 1
        for (int c = 0; c < 8; c++) {
            const int cb = c & 1;
            if (c < 7) {
                #pragma unroll
                for (int i = 0; i < 2; i++)
                    r[i] = *reinterpret_cast<const float4*>(
                        &hin[((c + 1) * KC + s_k0 + i * 64) * BSZ + btile + s_col]);
            }
            const float* hp = hs + cb * CHUNK_F + ksg * 32 + b_local;
            const float* wp = Ws + (c * KC + ksg) * WS_STRIDE + n_local;
            #pragma unroll 8
            for (int i = 0; i < 16; i++) {
                float4 h4 = *reinterpret_cast<const float4*>(hp + i * 256);
                ulonglong2 w2 = *reinterpret_cast<const ulonglong2*>(wp + i * 8 * WS_STRIDE);
                unsigned long long d0 = dupf(h4.x), d1 = dupf(h4.y);
                unsigned long long d2 = dupf(h4.z), d3 = dupf(h4.w);
                ffma2(acc[0][0], d0, w2.x); ffma2(acc[0][1], d0, w2.y);
                ffma2(acc[1][0], d1, w2.x); ffma2(acc[1][1], d1, w2.y);
                ffma2(acc[2][0], d2, w2.x); ffma2(acc[2][1], d2, w2.y);
                ffma2(acc[3][0], d3, w2.x); ffma2(acc[3][1], d3, w2.y);
            }
            if (c < 7) {
                #pragma unroll
                for (int i = 0; i < 2; i++)
                    *reinterpret_cast<float4*>(
                        &hs[(1 - cb) * CHUNK_F + (s_k0 + i * 64) * 32 + s_col]) = r[i];
                __syncthreads();
            }
        }

        // Phase A: groups 4..7 park into pbufA (buffer 0, dead during chunk 7).
        if (ksg >= 4) {
            #pragma unroll
            for (int j = 0; j < 8; j++)
                pbufA[j * 256 + (ksg - 4) * 64 + gt] = acc[j >> 1][j & 1];
        }
        __syncthreads();

        // Phase B+C: groups 0..3 fold partner partials, park into pbufB (buf 1,
        // dead now that chunk-7 compute is complete CTA-wide).
        if (ksg < 4) {
            #pragma unroll
            for (int j = 0; j < 8; j++) {
                add2(acc[j >> 1][j & 1], pbufA[j * 256 + ksg * 64 + gt]);
                pbufB[j * 256 + ksg * 64 + gt] = acc[j >> 1][j & 1];
            }
        }
        __syncthreads();

        // Phase D: all 512 threads, 1 (b, n-pair) output slot each.
        {
            unsigned long long s0 = pbufB[e_j * 256 + e_gt];
            #pragma unroll
            for (int g = 1; g < 4; g++)
                add2(s0, pbufB[e_j * 256 + g * 64 + e_gt]);
            float2 v = u64_to_f2(s0);
            float h0 = tanhf(v.x + xr.x);
            float h1 = tanhf(v.y + xr.y);

            const int bg = btile + e_bl;
            const int ng = ntile + e_nl;
            hout[(ng + 0) * BSZ + bg] = h0;
            hout[(ng + 1) * BSZ + bg] = h1;

            __syncthreads();   // all hout stores done CTA-wide
            if (tid == 0) {
                __threadfence();
                *(volatile unsigned*)fl_self = base + 2 + (unsigned)s;
            }

            // Decoder states: CTA-private, off the inter-CTA critical path.
            if (s >= 256) {
                *reinterpret_cast<float2*>(
                    &states[((size_t)bg * MAXLEN + t) * DHID + ng]) =
                    make_float2(h0, h1);
            }
        }
    }
}

// ---------------------------------------------------------------------------
// No-op pad (1x): keeps the persistent kernel in ncu's -s 5 -c 1 capture slot.
// ---------------------------------------------------------------------------
__global__ void noop_kernel() {}

// ---------------------------------------------------------------------------
// In-place row-wise log-softmax over VOC=512 columns. One warp per row.
// ---------------------------------------------------------------------------
__global__ void log_softmax_kernel(float* __restrict__ data)
{
    int gw   = (blockIdx.x * blockDim.x + threadIdx.x) >> 5;
    int lane = threadIdx.x & 31;
    if (gw >= BT) return;
    float* row = data + (size_t)gw * VOC;

    float v[16];
    float mx = -1e30f;
    #pragma unroll
    for (int i = 0; i < 16; i++) {
        v[i] = row[lane + i * 32];
        mx = fmaxf(mx, v[i]);
    }
    #pragma unroll
    for (int o = 16; o > 0; o >>= 1)
        mx = fmaxf(mx, __shfl_xor_sync(0xffffffffu, mx, o));

    float s = 0.0f;
    #pragma unroll
    for (int i = 0; i < 16; i++) s += expf(v[i] - mx);
    #pragma unroll
    for (int o = 16; o > 0; o >>= 1)
        s += __shfl_xor_sync(0xffffffffu, s, o);

    float lse = mx + logf(s);
    #pragma unroll
    for (int i = 0; i < 16; i++) row[lane + i * 32] = v[i] - lse;
}

// ---------------------------------------------------------------------------
extern "C" void kernel_launch(void* const* d_in, const int* in_sizes, int n_in,
                              void* d_out, int out_size)
{
    const int*   inputs  = (const int*)d_in[0];
    const int*   outputs = (const int*)d_in[1];
    const float* emb     = (const float*)d_in[2];
    const float* enc_Wih = (const float*)d_in[3];
    const float* enc_Whh = (const float*)d_in[4];
    const float* enc_bih = (const float*)d_in[5];
    const float* enc_bhh = (const float*)d_in[6];
    const float* dec_Wih = (const float*)d_in[7];
    const float* dec_Whh = (const float*)d_in[8];
    const float* dec_bih = (const float*)d_in[9];
    const float* dec_bhh = (const float*)d_in[10];
    const float* out_W   = (const float*)d_in[11];
    const float* out_b   = (const float*)d_in[12];
    float* out = (float*)d_out;

    float *xp_enc, *xp_dec, *states, *hT0, *hT1;
    cudaGetSymbolAddress((void**)&xp_enc, g_xp_enc);
    cudaGetSymbolAddress((void**)&xp_dec, g_xp_dec);
    cudaGetSymbolAddress((void**)&states, g_states);
    cudaGetSymbolAddress((void**)&hT0,    g_hT0);
    cudaGetSymbolAddress((void**)&hT1,    g_hT1);

    // Input projections (embedding gather fused): xp = emb[tok] @ Wih^T + bih + bhh
    gemm_gather_kernel<<<dim3(DHID / GBN, BT / GBM), 256>>>(
        emb, DCHAR, inputs, 1, MAXLEN, enc_Wih, enc_bih, enc_bhh, xp_enc, DHID, DCHAR);
    gemm_gather_kernel<<<dim3(DHID / GBN, BT / GBM), 256>>>(
        emb, DCHAR, outputs, 2, MAXLEN, dec_Wih, dec_bih, dec_bhh, xp_dec, DHID, DCHAR);

    // Single pad: persistent kernel lands in ncu's -s 5 -c 1 capture slot.
    noop_kernel<<<1, 32>>>();

    // Persistent recurrence: encoder 256 steps + decoder 256 steps, flag-synced.
    cudaFuncSetAttribute(rnn_persistent_kernel,
                         cudaFuncAttributeMaxDynamicSharedMemorySize, SMEM_BYTES);
    rnn_persistent_kernel<<<dim3(32, 4), NTHREADS, SMEM_BYTES>>>(
        xp_enc, xp_dec, enc_Whh, dec_Whh, states, hT0, hT1);

    // logits = states @ out_W^T + out_b -> d_out, then log-softmax in place.
    gemm_gather_kernel<<<dim3(VOC / GBN, BT / GBM), 256>>>(
        states, DHID, nullptr, 0, MAXLEN, out_W, out_b, nullptr, out, VOC, DHID);

    log_softmax_kernel<<<BT / 8, 256>>>(out);
}

// round 11
// speedup vs baseline: 1.2502x; 1.2502x over previous
#include <cuda_runtime.h>
#include <math.h>

#define BSZ    128
#define MAXLEN 256
#define DCHAR  256
#define DHID   1024
#define VOC    512
#define BT     (BSZ * MAXLEN)   // 32768
#define BH     (BSZ * DHID)     // 131072

// ---------------------------------------------------------------------------
// Scratch (allocation-free: __device__ globals)
// ---------------------------------------------------------------------------
__device__ float g_xp_enc[BT * DHID];
__device__ float g_xp_dec[BT * DHID];
__device__ float g_states[BT * DHID];
__device__ float g_hT0[DHID * BSZ];     // transposed hidden ping [k][b]
__device__ float g_hT1[DHID * BSZ];     // transposed hidden pong [k][b]

// Per-CTA publish flags: [mi][ni], 128B (32 u32) apart. Monotone across
// graph replays (each CTA advances its own flag by exactly 513 per run).
__device__ unsigned g_flag[4 * 32 * 32];

// ---------------------------------------------------------------------------
// f32x2 helpers
// ---------------------------------------------------------------------------
__device__ __forceinline__ unsigned long long dupf(float x)
{
    unsigned long long r;
    asm("mov.b64 %0,{%1,%1};" : "=l"(r) : "f"(x));
    return r;
}
__device__ __forceinline__ void ffma2(unsigned long long& a,
                                      unsigned long long x, unsigned long long y)
{
    asm("fma.rn.f32x2 %0,%1,%2,%0;" : "+l"(a) : "l"(x), "l"(y));
}
__device__ __forceinline__ void add2(unsigned long long& a, unsigned long long x)
{
    asm("add.rn.f32x2 %0,%0,%1;" : "+l"(a) : "l"(x));
}
__device__ __forceinline__ float2 u64_to_f2(unsigned long long v)
{
    float2 f;
    asm("mov.b64 {%0,%1},%2;" : "=f"(f.x), "=f"(f.y) : "l"(v));
    return f;
}
__device__ __forceinline__ unsigned ld_acq(const unsigned* p)
{
    unsigned v;
    asm volatile("ld.acquire.gpu.global.u32 %0,[%1];" : "=r"(v) : "l"(p) : "memory");
    return v;
}

// ---------------------------------------------------------------------------
// Tiled SGEMM with row gather, v6: CTA tile 128x128, 256 threads, 8x8 thread
// tiles. Per k per thread: 4 LDS.128 + 8 dup MOV + 32 FFMA2 -> crossbar:FMA
// balanced 1:1 (v5 was 2:1 crossbar-bound).
//   C[row, n] = sum_k A[src(row), k] * B[n, k] + bias1[n] (+ bias2[n])
// ---------------------------------------------------------------------------
#define GBM 128
#define GBN 128
#define GBK 16
#define GAS 132   // padded row stride (floats); 132*4=528 = 33*16 (16B aligned)

__global__ void __launch_bounds__(256)
gemm_gather_kernel(const float* __restrict__ A, int lda,
                   const int* __restrict__ tokens, int gmode, int T,
                   const float* __restrict__ B,
                   const float* __restrict__ bias1,
                   const float* __restrict__ bias2,
                   float* __restrict__ C,
                   int N, int K)
{
    __shared__ __align__(16) float As[GBK][GAS];
    __shared__ __align__(16) float Bs[GBK][GAS];
    __shared__ int rowsrc[GBM];

    const int bm  = blockIdx.y * GBM;
    const int bn  = blockIdx.x * GBN;
    const int tid = threadIdx.x;

    if (tid < GBM) {
        int row = bm + tid;
        int src = row;
        if (gmode == 1) {
            src = tokens[row];
        } else if (gmode == 2) {
            int t = row % T;
            src = (t == 0) ? -1 : tokens[row - 1];
        }
        rowsrc[tid] = src;
    }
    __syncthreads();

    const int tm = (tid >> 4) * 8;   // 0..120
    const int tn = (tid & 15) * 8;   // 0..120

    unsigned long long acc[4][8] = {};   // [m-pair][n]

    for (int k0 = 0; k0 < K; k0 += GBK) {
        // Stage A,B: 2048 elems each; idx -> (m = idx>>4, kk = idx&15):
        // consecutive threads read consecutive kk of one row (coalesced LDG).
        #pragma unroll
        for (int i = 0; i < 8; i++) {
            int idx = tid + i * 256;
            int m = idx >> 4, kk = idx & 15;
            int src = rowsrc[m];
            As[kk][m] = (src < 0) ? 0.0f : A[src * lda + k0 + kk];
        }
        #pragma unroll
        for (int i = 0; i < 8; i++) {
            int idx = tid + i * 256;
            int n = idx >> 4, kk = idx & 15;
            Bs[kk][n] = B[(bn + n) * K + k0 + kk];
        }
        __syncthreads();

        #pragma unroll
        for (int kk = 0; kk < GBK; kk++) {
            ulonglong2 aA = *reinterpret_cast<const ulonglong2*>(&As[kk][tm]);
            ulonglong2 aB = *reinterpret_cast<const ulonglong2*>(&As[kk][tm + 4]);
            float4 b4A = *reinterpret_cast<const float4*>(&Bs[kk][tn]);
            float4 b4B = *reinterpret_cast<const float4*>(&Bs[kk][tn + 4]);
            unsigned long long bd[8];
            bd[0] = dupf(b4A.x); bd[1] = dupf(b4A.y);
            bd[2] = dupf(b4A.z); bd[3] = dupf(b4A.w);
            bd[4] = dupf(b4B.x); bd[5] = dupf(b4B.y);
            bd[6] = dupf(b4B.z); bd[7] = dupf(b4B.w);
            unsigned long long ap[4] = {aA.x, aA.y, aB.x, aB.y};
            #pragma unroll
            for (int mp = 0; mp < 4; mp++)
                #pragma unroll
                for (int j = 0; j < 8; j++)
                    ffma2(acc[mp][j], ap[mp], bd[j]);
        }
        __syncthreads();
    }

    // Epilogue: unpack to rows, add bias, 2x float4 store per row.
    float bb[8];
    #pragma unroll
    for (int j = 0; j < 8; j++) {
        int n = bn + tn + j;
        bb[j] = (bias1 ? bias1[n] : 0.0f) + (bias2 ? bias2[n] : 0.0f);
    }
    #pragma unroll
    for (int mp = 0; mp < 4; mp++) {
        float r0[8], r1[8];
        #pragma unroll
        for (int j = 0; j < 8; j++) {
            float2 v = u64_to_f2(acc[mp][j]);
            r0[j] = v.x + bb[j];
            r1[j] = v.y + bb[j];
        }
        float* c0 = &C[(size_t)(bm + tm + mp * 2 + 0) * N + bn + tn];
        float* c1 = &C[(size_t)(bm + tm + mp * 2 + 1) * N + bn + tn];
        *reinterpret_cast<float4*>(c0)     = make_float4(r0[0], r0[1], r0[2], r0[3]);
        *reinterpret_cast<float4*>(c0 + 4) = make_float4(r0[4], r0[5], r0[6], r0[7]);
        *reinterpret_cast<float4*>(c1)     = make_float4(r1[0], r1[1], r1[2], r1[3]);
        *reinterpret_cast<float4*>(c1 + 4) = make_float4(r1[4], r1[5], r1[6], r1[7]);
    }
}

// ---------------------------------------------------------------------------
// Persistent recurrence kernel, v8: 256 threads, 16-way interleaved split-k,
// 8b x 8n register tiles. Per k-iter per thread: 4 LDS.128 + 8 MOV + 32 FFMA2
// -> GEMM crossbar 8192 phases/step (halved vs v6/v7), = FFMA2 floor.
// Reduction: warp shfl-fold (16->8 partials), park into dedicated padded smem,
// all-256-thread final reduce + tanh + store.
// ---------------------------------------------------------------------------
#define WS_STRIDE 36
#define WS_F      (DHID * WS_STRIDE)    // 36864 floats (144 KB)
#define KC        128                   // staged k-chunk
#define CHUNK_F   (KC * 32)             // 4096 floats (16 KB)
#define PARK_F    (WS_F + 2 * CHUNK_F)  // float offset of park buffer
#define PARK_U64  4640                  // 32*145 + pad (37120 B)
#define SMEM_BYTES (PARK_F * 4 + PARK_U64 * 8)   // 217344 B

__device__ __forceinline__ void load_whh_slice(float* Ws, const float* __restrict__ W,
                                               int ntile, int tid)
{
    for (int idx = tid; idx < 32 * 256; idx += 256) {
        int row = idx >> 8;          // 0..31 (n local)
        int c4  = idx & 255;         // 0..255 (k/4)
        float4 v = *reinterpret_cast<const float4*>(&W[(ntile + row) * DHID + c4 * 4]);
        int k = c4 * 4;
        Ws[(k + 0) * WS_STRIDE + row] = v.x;
        Ws[(k + 1) * WS_STRIDE + row] = v.y;
        Ws[(k + 2) * WS_STRIDE + row] = v.z;
        Ws[(k + 3) * WS_STRIDE + row] = v.w;
    }
}

__global__ void __launch_bounds__(256, 1)
rnn_persistent_kernel(const float* __restrict__ xp_enc,
                      const float* __restrict__ xp_dec,
                      const float* __restrict__ enc_Whh,
                      const float* __restrict__ dec_Whh,
                      float* __restrict__ states,
                      float* __restrict__ hT0,
                      float* __restrict__ hT1)
{
    extern __shared__ float sm[];
    float* Ws = sm;                       // [1024][36]
    float* hs = sm + WS_F;                // 2 x [128 k][32 b]
    unsigned long long* park =
        reinterpret_cast<unsigned long long*>(sm + PARK_F);  // dedicated, padded

    const int tid = threadIdx.x;
    const int ni = blockIdx.x, mi = blockIdx.y;
    const int btile = mi * 32, ntile = ni * 32;

    unsigned* const fl_grp  = &g_flag[mi * 32 * 32];
    unsigned* const fl_self = fl_grp + ni * 32;

    const int ksg  = tid >> 4;            // 0..15 : k ≡ ksg (mod 16)
    const int g    = tid & 15;            // within-ksg output block
    const int bpos = (g & 3) * 8;         // 8 batch rows
    const int npos = (g >> 2) * 8;        // 8 hidden cols

    const int wrp = tid >> 5;             // warp id (0..7)
    const int lg  = tid & 31;             // lane

    // Staging decomposition: 1024 float4 slots, 4 per thread.
    const int s_kl  = tid >> 3;           // base k row (0..31), +32 per i
    const int s_col = (tid & 7) * 4;      // b column

    // Final-epilogue output slots: o = tid and tid+256 (o = g'*32 + jj).
    const int o1g = tid >> 5,          o1j = tid & 31;
    const int o2g = (tid + 256) >> 5,  o2j = tid & 31;
    const int b1 = (o1g & 3) * 8 + (o1j >> 2), n1 = (o1g >> 2) * 8 + (o1j & 3) * 2;
    const int b2 = (o2g & 3) * 8 + (o2j >> 2), n2 = (o2g >> 2) * 8 + (o2j & 3) * 2;

    __shared__ unsigned s_base;
    if (tid == 0) s_base = *(volatile unsigned*)fl_self;

    // Zero this CTA's h0 slice: k in [ntile,+32), b in [btile,+32) = 256 float4.
    {
        int k = ntile + (tid >> 3);
        int col = (tid & 7) * 4;
        *reinterpret_cast<float4*>(&hT0[k * BSZ + btile + col]) =
            make_float4(0.f, 0.f, 0.f, 0.f);
    }
    __syncthreads();
    const unsigned base = s_base;

    if (tid == 0) {                    // publish h^0 (zeros)
        __threadfence();
        *(volatile unsigned*)fl_self = base + 1;
    }

    load_whh_slice(Ws, enc_Whh, ntile, tid);
    __syncthreads();

    for (int s = 0; s < 512; s++) {
        if (s == 256) {
            load_whh_slice(Ws, dec_Whh, ntile, tid);
            __syncthreads();
        }
        const float* __restrict__ hin  = (s & 1) ? hT1 : hT0;
        float* __restrict__       hout = (s & 1) ? hT0 : hT1;
        const int t = s & 255;
        const float* __restrict__ xp = (s < 256) ? xp_enc : xp_dec;
        const unsigned tgt = base + 1 + (unsigned)s;

        // Epilogue xp prefetch (independent of flags).
        float2 xr1 = *reinterpret_cast<const float2*>(
            &xp[((size_t)(btile + b1) * MAXLEN + t) * DHID + ntile + n1]);
        float2 xr2 = *reinterpret_cast<const float2*>(
            &xp[((size_t)(btile + b2) * MAXLEN + t) * DHID + ntile + n2]);

        // Warp-parallel wait: lane j of warp 0 polls producer flag j.
        if (tid < 32) {
            const unsigned* p = fl_grp + tid * 32;
            unsigned v = ld_acq(p);
            while (!__all_sync(0xffffffffu, (int)(v - tgt) >= 0))
                v = ld_acq(p);
        }
        __syncthreads();

        // Stage chunk 0.
        float4 r[4];
        #pragma unroll
        for (int i = 0; i < 4; i++)
            r[i] = *reinterpret_cast<const float4*>(
                &hin[(s_kl + i * 32) * BSZ + btile + s_col]);
        #pragma unroll
        for (int i = 0; i < 4; i++)
            *reinterpret_cast<float4*>(&hs[(s_kl + i * 32) * 32 + s_col]) = r[i];
        __syncthreads();

        unsigned long long acc[32] = {};   // [b(8)][n-pair(4)] = b*4+np

        #pragma unroll 1
        for (int c = 0; c < 8; c++) {
            const int cb = c & 1;
            if (c < 7) {
                #pragma unroll
                for (int i = 0; i < 4; i++)
                    r[i] = *reinterpret_cast<const float4*>(
                        &hin[((c + 1) * KC + s_kl + i * 32) * BSZ + btile + s_col]);
            }
            const float* hp = hs + cb * CHUNK_F + ksg * 32 + bpos;
            const float* wp = Ws + (c * KC + ksg) * WS_STRIDE + npos;
            #pragma unroll
            for (int i = 0; i < 8; i++) {          // k = c*128 + i*16 + ksg
                const float* hpp = hp + i * (16 * 32);
                const float* wpp = wp + i * (16 * WS_STRIDE);
                float4 hA = *reinterpret_cast<const float4*>(hpp);
                float4 hB = *reinterpret_cast<const float4*>(hpp + 4);
                ulonglong2 wA = *reinterpret_cast<const ulonglong2*>(wpp);
                ulonglong2 wB = *reinterpret_cast<const ulonglong2*>(wpp + 4);
                float hv[8] = {hA.x, hA.y, hA.z, hA.w, hB.x, hB.y, hB.z, hB.w};
                #pragma unroll
                for (int b = 0; b < 8; b++) {
                    unsigned long long hd = dupf(hv[b]);
                    ffma2(acc[b * 4 + 0], hd, wA.x);
                    ffma2(acc[b * 4 + 1], hd, wA.y);
                    ffma2(acc[b * 4 + 2], hd, wB.x);
                    ffma2(acc[b * 4 + 3], hd, wB.y);
                }
            }
            if (c < 7) {
                #pragma unroll
                for (int i = 0; i < 4; i++)
                    *reinterpret_cast<float4*>(
                        &hs[(1 - cb) * CHUNK_F + (s_kl + i * 32) * 32 + s_col]) = r[i];
                __syncthreads();
            }
        }

        // Warp fold: lane l and l^16 hold the same (g, jj) for sibling ksg.
        #pragma unroll
        for (int jj = 0; jj < 32; jj++) {
            unsigned long long o = __shfl_xor_sync(0xffffffffu, acc[jj], 16);
            add2(acc[jj], o);
        }

        // Park: warp wrp, lanes 0..15 (lane = g) store 32 u64 each.
        if (lg < 16) {
            #pragma unroll
            for (int jj = 0; jj < 32; jj++)
                park[jj * 145 + lg * 9 + wrp] = acc[jj];
        }
        __syncthreads();

        // Final: each thread reduces 8 warp-partials for 2 output u64s.
        {
            unsigned long long s1 = park[o1j * 145 + o1g * 9];
            unsigned long long s2 = park[o2j * 145 + o2g * 9];
            #pragma unroll
            for (int w = 1; w < 8; w++) {
                add2(s1, park[o1j * 145 + o1g * 9 + w]);
                add2(s2, park[o2j * 145 + o2g * 9 + w]);
            }
            float2 v1 = u64_to_f2(s1), v2 = u64_to_f2(s2);
            float h10 = tanhf(v1.x + xr1.x), h11 = tanhf(v1.y + xr1.y);
            float h20 = tanhf(v2.x + xr2.x), h21 = tanhf(v2.y + xr2.y);

            hout[(ntile + n1 + 0) * BSZ + btile + b1] = h10;
            hout[(ntile + n1 + 1) * BSZ + btile + b1] = h11;
            hout[(ntile + n2 + 0) * BSZ + btile + b2] = h20;
            hout[(ntile + n2 + 1) * BSZ + btile + b2] = h21;

            __syncthreads();   // all hout stores done CTA-wide
            if (tid == 0) {
                __threadfence();
                *(volatile unsigned*)fl_self = base + 2 + (unsigned)s;
            }

            // Decoder states: CTA-private, off the inter-CTA critical path.
            if (s >= 256) {
                *reinterpret_cast<float2*>(
                    &states[((size_t)(btile + b1) * MAXLEN + t) * DHID + ntile + n1]) =
                    make_float2(h10, h11);
                *reinterpret_cast<float2*>(
                    &states[((size_t)(btile + b2) * MAXLEN + t) * DHID + ntile + n2]) =
                    make_float2(h20, h21);
            }
        }
    }
}

// ---------------------------------------------------------------------------
// No-op pad (1x): keeps the persistent kernel in ncu's -s 5 -c 1 capture slot.
// ---------------------------------------------------------------------------
__global__ void noop_kernel() {}

// ---------------------------------------------------------------------------
// In-place row-wise log-softmax over VOC=512 columns. One warp per row.
// ---------------------------------------------------------------------------
__global__ void log_softmax_kernel(float* __restrict__ data)
{
    int gw   = (blockIdx.x * blockDim.x + threadIdx.x) >> 5;
    int lane = threadIdx.x & 31;
    if (gw >= BT) return;
    float* row = data + (size_t)gw * VOC;

    float v[16];
    float mx = -1e30f;
    #pragma unroll
    for (int i = 0; i < 16; i++) {
        v[i] = row[lane + i * 32];
        mx = fmaxf(mx, v[i]);
    }
    #pragma unroll
    for (int o = 16; o > 0; o >>= 1)
        mx = fmaxf(mx, __shfl_xor_sync(0xffffffffu, mx, o));

    float s = 0.0f;
    #pragma unroll
    for (int i = 0; i < 16; i++) s += expf(v[i] - mx);
    #pragma unroll
    for (int o = 16; o > 0; o >>= 1)
        s += __shfl_xor_sync(0xffffffffu, s, o);

    float lse = mx + logf(s);
    #pragma unroll
    for (int i = 0; i < 16; i++) row[lane + i * 32] = v[i] - lse;
}

// ---------------------------------------------------------------------------
extern "C" void kernel_launch(void* const* d_in, const int* in_sizes, int n_in,
                              void* d_out, int out_size)
{
    const int*   inputs  = (const int*)d_in[0];
    const int*   outputs = (const int*)d_in[1];
    const float* emb     = (const float*)d_in[2];
    const float* enc_Wih = (const float*)d_in[3];
    const float* enc_Whh = (const float*)d_in[4];
    const float* enc_bih = (const float*)d_in[5];
    const float* enc_bhh = (const float*)d_in[6];
    const float* dec_Wih = (const float*)d_in[7];
    const float* dec_Whh = (const float*)d_in[8];
    const float* dec_bih = (const float*)d_in[9];
    const float* dec_bhh = (const float*)d_in[10];
    const float* out_W   = (const float*)d_in[11];
    const float* out_b   = (const float*)d_in[12];
    float* out = (float*)d_out;

    float *xp_enc, *xp_dec, *states, *hT0, *hT1;
    cudaGetSymbolAddress((void**)&xp_enc, g_xp_enc);
    cudaGetSymbolAddress((void**)&xp_dec, g_xp_dec);
    cudaGetSymbolAddress((void**)&states, g_states);
    cudaGetSymbolAddress((void**)&hT0,    g_hT0);
    cudaGetSymbolAddress((void**)&hT1,    g_hT1);

    // Input projections (embedding gather fused): xp = emb[tok] @ Wih^T + bih + bhh
    gemm_gather_kernel<<<dim3(DHID / GBN, BT / GBM), 256>>>(
        emb, DCHAR, inputs, 1, MAXLEN, enc_Wih, enc_bih, enc_bhh, xp_enc, DHID, DCHAR);
    gemm_gather_kernel<<<dim3(DHID / GBN, BT / GBM), 256>>>(
        emb, DCHAR, outputs, 2, MAXLEN, dec_Wih, dec_bih, dec_bhh, xp_dec, DHID, DCHAR);

    // Single pad: persistent kernel lands in ncu's -s 5 -c 1 capture slot.
    noop_kernel<<<1, 32>>>();

    // Persistent recurrence: encoder 256 steps + decoder 256 steps, flag-synced.
    cudaFuncSetAttribute(rnn_persistent_kernel,
                         cudaFuncAttributeMaxDynamicSharedMemorySize, SMEM_BYTES);
    rnn_persistent_kernel<<<dim3(32, 4), 256, SMEM_BYTES>>>(
        xp_enc, xp_dec, enc_Whh, dec_Whh, states, hT0, hT1);

    // logits = states @ out_W^T + out_b -> d_out, then log-softmax in place.
    gemm_gather_kernel<<<dim3(VOC / GBN, BT / GBM), 256>>>(
        states, DHID, nullptr, 0, MAXLEN, out_W, out_b, nullptr, out, VOC, DHID);

    log_softmax_kernel<<<BT / 8, 256>>>(out);
}